// round 5
// baseline (speedup 1.0000x reference)
#include <cuda_runtime.h>
#include <cuda_bf16.h>
#include <math.h>

// Problem constants (fixed by the reference)
#define N0   100000
#define N1   200000
#define NNZE 400000
#define DIN  256
#define DOUT 256

// Scratch for msg = x_0 @ W  (102.4 MB). __device__ global: allocation-free.
__device__ float g_msg[(size_t)N0 * DOUT];

// ---------------------------------------------------------------------------
// Kernel 1: fp32 SGEMM  g_msg[M,256] = A[M,256] @ W[256,256]
// 128x128 block tile, BK=16, 256 threads, 8x8 micro-tile per thread,
// split as 2x(4) row groups and 2x(4) col groups (conflict-free LDS.128).
// ---------------------------------------------------------------------------
__global__ __launch_bounds__(256, 2)
void sgemm_kernel(const float* __restrict__ A, const float* __restrict__ W)
{
    __shared__ float As[16][128];   // A tile, transposed: As[k][m]
    __shared__ float Bs[16][128];   // B tile: Bs[k][n]

    const int tid = threadIdx.x;
    const int tx  = tid & 15;       // 0..15  -> col groups tx*4, tx*4+64
    const int ty  = tid >> 4;       // 0..15  -> row groups ty*4, ty*4+64

    const int blockRow = blockIdx.y * 128;
    const int blockCol = blockIdx.x * 128;

    float acc[8][8];
    #pragma unroll
    for (int i = 0; i < 8; i++)
        #pragma unroll
        for (int j = 0; j < 8; j++) acc[i][j] = 0.0f;

    for (int kt = 0; kt < DIN; kt += 16) {
        // Load A tile: 128 rows x 16 cols, store transposed.
        #pragma unroll
        for (int i = 0; i < 2; i++) {
            int idx  = tid + i * 256;        // 0..511 float4 slots
            int arow = idx >> 2;             // 0..127
            int ac4  = (idx & 3) * 4;        // 0,4,8,12
            int grow = blockRow + arow;
            float4 v = make_float4(0.f, 0.f, 0.f, 0.f);
            if (grow < N0)
                v = *(const float4*)(A + (size_t)grow * DIN + kt + ac4);
            As[ac4 + 0][arow] = v.x;
            As[ac4 + 1][arow] = v.y;
            As[ac4 + 2][arow] = v.z;
            As[ac4 + 3][arow] = v.w;
        }
        // Load B tile: 16 rows x 128 cols (coalesced float4).
        #pragma unroll
        for (int i = 0; i < 2; i++) {
            int idx  = tid + i * 256;        // 0..511
            int brow = idx >> 5;             // 0..15
            int bc4  = (idx & 31) * 4;       // 0..124
            float4 v = *(const float4*)(W + (size_t)(kt + brow) * DOUT + blockCol + bc4);
            *(float4*)&Bs[brow][bc4] = v;
        }
        __syncthreads();

        #pragma unroll
        for (int kk = 0; kk < 16; kk++) {
            float4 a0 = *(float4*)&As[kk][ty * 4];
            float4 a1 = *(float4*)&As[kk][ty * 4 + 64];
            float4 b0 = *(float4*)&Bs[kk][tx * 4];
            float4 b1 = *(float4*)&Bs[kk][tx * 4 + 64];
            float a[8] = {a0.x, a0.y, a0.z, a0.w, a1.x, a1.y, a1.z, a1.w};
            float b[8] = {b0.x, b0.y, b0.z, b0.w, b1.x, b1.y, b1.z, b1.w};
            #pragma unroll
            for (int i = 0; i < 8; i++)
                #pragma unroll
                for (int j = 0; j < 8; j++)
                    acc[i][j] = fmaf(a[i], b[j], acc[i][j]);
        }
        __syncthreads();
    }

    // Store C: rows {ty*4..+3, +64} x cols {tx*4..+3, +64}
    #pragma unroll
    for (int ih = 0; ih < 2; ih++) {
        #pragma unroll
        for (int i = 0; i < 4; i++) {
            int row = blockRow + ih * 64 + ty * 4 + i;
            if (row < N0) {
                float* cp = g_msg + (size_t)row * DOUT + blockCol;
                int ai = ih * 4 + i;
                *(float4*)(cp + tx * 4)      = make_float4(acc[ai][0], acc[ai][1], acc[ai][2], acc[ai][3]);
                *(float4*)(cp + 64 + tx * 4) = make_float4(acc[ai][4], acc[ai][5], acc[ai][6], acc[ai][7]);
            }
        }
    }
}

// ---------------------------------------------------------------------------
// Kernel 2: scatter-add. One warp per edge. Each lane handles 2 float4
// (256 floats / 32 lanes = 8). 128-bit vector atomics (sm_90+ native).
// ---------------------------------------------------------------------------
__global__ __launch_bounds__(256)
void scatter_kernel(const int* __restrict__ rows,
                    const int* __restrict__ cols,
                    const float* __restrict__ vals,
                    float* __restrict__ out)
{
    int edge = (blockIdx.x * blockDim.x + threadIdx.x) >> 5;
    int lane = threadIdx.x & 31;
    if (edge >= NNZE) return;

    int   r = rows[edge];
    int   c = cols[edge];
    float v = vals[edge];

    const float4* src = (const float4*)(g_msg + (size_t)c * DOUT);
    float4*       dst = (float4*)(out + (size_t)r * DOUT);

    #pragma unroll
    for (int i = 0; i < 2; i++) {
        int k = lane + i * 32;       // 0..63 float4 per row
        float4 p = src[k];
        p.x *= v; p.y *= v; p.z *= v; p.w *= v;
        atomicAdd(dst + k, p);       // 128-bit REDG
    }
}

// ---------------------------------------------------------------------------
// Kernel 3: in-place ELU over the aggregated output.
// ---------------------------------------------------------------------------
__global__ __launch_bounds__(256)
void elu_kernel(float* __restrict__ out)
{
    size_t i = (size_t)blockIdx.x * blockDim.x + threadIdx.x;
    const size_t total4 = (size_t)N1 * DOUT / 4;
    if (i >= total4) return;
    float4* p = (float4*)out;
    float4 v = p[i];
    v.x = v.x > 0.f ? v.x : expm1f(v.x);
    v.y = v.y > 0.f ? v.y : expm1f(v.y);
    v.z = v.z > 0.f ? v.z : expm1f(v.z);
    v.w = v.w > 0.f ? v.w : expm1f(v.w);
    p[i] = v;
}

// ---------------------------------------------------------------------------
// Launch: inputs per metadata order: x_0, x_1(unused), nb_rows, nb_cols,
// nb_vals, weight. Output: float32 [N1, DOUT].
// ---------------------------------------------------------------------------
extern "C" void kernel_launch(void* const* d_in, const int* in_sizes, int n_in,
                              void* d_out, int out_size)
{
    const float* x_0     = (const float*)d_in[0];
    const int*   nb_rows = (const int*)  d_in[2];
    const int*   nb_cols = (const int*)  d_in[3];
    const float* nb_vals = (const float*)d_in[4];
    const float* weight  = (const float*)d_in[5];
    float*       out     = (float*)d_out;

    // Zero the accumulation buffer (memset nodes are graph-capturable).
    cudaMemsetAsync(out, 0, (size_t)out_size * sizeof(float), 0);

    // GEMM: grid (N/128, ceil(M/128))
    dim3 ggrid(DOUT / 128, (N0 + 127) / 128);
    sgemm_kernel<<<ggrid, 256>>>(x_0, weight);

    // Scatter: 8 warps (edges) per 256-thread block.
    int sblocks = (NNZE + 7) / 8;
    scatter_kernel<<<sblocks, 256>>>(nb_rows, nb_cols, nb_vals, out);

    // ELU epilogue.
    size_t total4 = (size_t)N1 * DOUT / 4;
    int eblocks = (int)((total4 + 255) / 256);
    elu_kernel<<<eblocks, 256>>>(out);
}

// round 6
// speedup vs baseline: 1.2909x; 1.2909x over previous
#include <cuda_runtime.h>
#include <cuda_bf16.h>
#include <math.h>

// Problem constants (fixed by the reference)
#define N0   100000
#define N1   200000
#define NNZE 400000
#define DIN  256
#define DOUT 256

#define SCAN_B 1024
#define NB_SCAN ((N1 + SCAN_B - 1) / SCAN_B)   // 196

// Scratch (allocation-free __device__ globals)
__device__ float g_msg[(size_t)N0 * DOUT];     // 102.4 MB
__device__ int   g_count[N1];
__device__ int   g_off[N1 + 1];
__device__ int   g_cursor[N1];
__device__ int   g_perm[NNZE];
__device__ int   g_bsum[256];
__device__ int   g_boff[256];

typedef unsigned long long u64;

__device__ __forceinline__ u64 pack2(float lo, float hi) {
    u64 r;
    asm("mov.b64 %0, {%1, %2};" : "=l"(r)
        : "r"(__float_as_uint(lo)), "r"(__float_as_uint(hi)));
    return r;
}
__device__ __forceinline__ void fma2(u64& d, u64 a, u64 b) {
    asm("fma.rn.f32x2 %0, %1, %2, %0;" : "+l"(d) : "l"(a), "l"(b));
}
__device__ __forceinline__ float2 unpack2(u64 v) {
    unsigned lo, hi;
    asm("mov.b64 {%0, %1}, %2;" : "=r"(lo), "=r"(hi) : "l"(v));
    return make_float2(__uint_as_float(lo), __uint_as_float(hi));
}

// ---------------------------------------------------------------------------
// Kernel 1: fp32 SGEMM  g_msg = A[M,256] @ W[256,256]
// 128x128 tile, BK=16, 256 threads, 8x8 micro-tile using packed f32x2 FMA.
// ---------------------------------------------------------------------------
__global__ __launch_bounds__(256, 2)
void sgemm_kernel(const float* __restrict__ A, const float* __restrict__ W)
{
    __shared__ float As[16][128];   // A tile transposed: As[k][m]
    __shared__ float Bs[16][128];   // B tile: Bs[k][n]

    const int tid = threadIdx.x;
    const int tx  = tid & 15;       // col groups tx*4, tx*4+64
    const int ty  = tid >> 4;       // row groups ty*4, ty*4+64

    const int blockRow = blockIdx.y * 128;
    const int blockCol = blockIdx.x * 128;

    // acc2[i][j]: rows i (0..7 -> ty*4+{0..3}, +64), col-pairs j
    // j=0,1 -> cols tx*4+{0,1},{2,3}; j=2,3 -> cols tx*4+64+{0,1},{2,3}
    u64 acc2[8][4];
    #pragma unroll
    for (int i = 0; i < 8; i++)
        #pragma unroll
        for (int j = 0; j < 4; j++) acc2[i][j] = 0ULL;

    for (int kt = 0; kt < DIN; kt += 16) {
        #pragma unroll
        for (int i = 0; i < 2; i++) {
            int idx  = tid + i * 256;        // 0..511 float4 slots
            int arow = idx >> 2;             // 0..127
            int ac4  = (idx & 3) * 4;        // 0,4,8,12
            int grow = blockRow + arow;
            float4 v = make_float4(0.f, 0.f, 0.f, 0.f);
            if (grow < N0)
                v = *(const float4*)(A + (size_t)grow * DIN + kt + ac4);
            As[ac4 + 0][arow] = v.x;
            As[ac4 + 1][arow] = v.y;
            As[ac4 + 2][arow] = v.z;
            As[ac4 + 3][arow] = v.w;
        }
        #pragma unroll
        for (int i = 0; i < 2; i++) {
            int idx  = tid + i * 256;
            int brow = idx >> 5;             // 0..15
            int bc4  = (idx & 31) * 4;       // 0..124
            float4 v = *(const float4*)(W + (size_t)(kt + brow) * DOUT + blockCol + bc4);
            *(float4*)&Bs[brow][bc4] = v;
        }
        __syncthreads();

        #pragma unroll
        for (int kk = 0; kk < 16; kk++) {
            float4 a0 = *(float4*)&As[kk][ty * 4];
            float4 a1 = *(float4*)&As[kk][ty * 4 + 64];
            float4 b0 = *(float4*)&Bs[kk][tx * 4];
            float4 b1 = *(float4*)&Bs[kk][tx * 4 + 64];
            u64 bp[4];
            bp[0] = pack2(b0.x, b0.y);
            bp[1] = pack2(b0.z, b0.w);
            bp[2] = pack2(b1.x, b1.y);
            bp[3] = pack2(b1.z, b1.w);
            float av[8] = {a0.x, a0.y, a0.z, a0.w, a1.x, a1.y, a1.z, a1.w};
            #pragma unroll
            for (int i = 0; i < 8; i++) {
                u64 ad = pack2(av[i], av[i]);
                fma2(acc2[i][0], ad, bp[0]);
                fma2(acc2[i][1], ad, bp[1]);
                fma2(acc2[i][2], ad, bp[2]);
                fma2(acc2[i][3], ad, bp[3]);
            }
        }
        __syncthreads();
    }

    #pragma unroll
    for (int ih = 0; ih < 2; ih++) {
        #pragma unroll
        for (int i = 0; i < 4; i++) {
            int row = blockRow + ih * 64 + ty * 4 + i;
            if (row < N0) {
                float* cp = g_msg + (size_t)row * DOUT + blockCol;
                int ai = ih * 4 + i;
                float2 c0 = unpack2(acc2[ai][0]);
                float2 c1 = unpack2(acc2[ai][1]);
                float2 c2 = unpack2(acc2[ai][2]);
                float2 c3 = unpack2(acc2[ai][3]);
                *(float4*)(cp + tx * 4)      = make_float4(c0.x, c0.y, c1.x, c1.y);
                *(float4*)(cp + 64 + tx * 4) = make_float4(c2.x, c2.y, c3.x, c3.y);
            }
        }
    }
}

// ---------------------------------------------------------------------------
// CSR build: zero counts -> histogram -> block scan -> scan of block sums ->
// add offsets (+init cursor) -> fill permutation.
// ---------------------------------------------------------------------------
__global__ __launch_bounds__(256)
void zero_count_kernel()
{
    int i = blockIdx.x * blockDim.x + threadIdx.x;
    if (i < N1) g_count[i] = 0;
}

__global__ __launch_bounds__(256)
void count_kernel(const int* __restrict__ rows)
{
    int e = blockIdx.x * blockDim.x + threadIdx.x;
    if (e < NNZE) atomicAdd(&g_count[rows[e]], 1);
}

__global__ __launch_bounds__(SCAN_B)
void scan1_kernel()
{
    __shared__ int s[SCAN_B];
    int tid = threadIdx.x;
    int i = blockIdx.x * SCAN_B + tid;
    int v = (i < N1) ? g_count[i] : 0;
    s[tid] = v;
    __syncthreads();
    #pragma unroll
    for (int off = 1; off < SCAN_B; off <<= 1) {
        int t = (tid >= off) ? s[tid - off] : 0;
        __syncthreads();
        s[tid] += t;
        __syncthreads();
    }
    if (i < N1) g_off[i] = s[tid] - v;          // block-local exclusive
    if (tid == SCAN_B - 1) g_bsum[blockIdx.x] = s[tid];
}

__global__ __launch_bounds__(256)
void scan2_kernel()
{
    __shared__ int s[256];
    int tid = threadIdx.x;
    int v = (tid < NB_SCAN) ? g_bsum[tid] : 0;
    s[tid] = v;
    __syncthreads();
    #pragma unroll
    for (int off = 1; off < 256; off <<= 1) {
        int t = (tid >= off) ? s[tid - off] : 0;
        __syncthreads();
        s[tid] += t;
        __syncthreads();
    }
    if (tid < NB_SCAN) g_boff[tid] = s[tid] - v;   // exclusive
}

__global__ __launch_bounds__(SCAN_B)
void scan3_kernel()
{
    int tid = threadIdx.x;
    int i = blockIdx.x * SCAN_B + tid;
    if (i < N1) {
        int val = g_off[i] + g_boff[blockIdx.x];
        g_off[i]    = val;
        g_cursor[i] = val;
    }
    if (i == 0) g_off[N1] = NNZE;
}

__global__ __launch_bounds__(256)
void fill_kernel(const int* __restrict__ rows)
{
    int e = blockIdx.x * blockDim.x + threadIdx.x;
    if (e < NNZE) {
        int pos = atomicAdd(&g_cursor[rows[e]], 1);
        g_perm[pos] = e;
    }
}

// ---------------------------------------------------------------------------
// Aggregation: one warp per output row. Atomic-free, ELU fused, single write.
// ---------------------------------------------------------------------------
__global__ __launch_bounds__(256)
void aggregate_kernel(const int* __restrict__ cols,
                      const float* __restrict__ vals,
                      float* __restrict__ out)
{
    int row  = (blockIdx.x * blockDim.x + threadIdx.x) >> 5;
    int lane = threadIdx.x & 31;
    if (row >= N1) return;

    int beg = g_off[row];
    int end = g_off[row + 1];

    float4 acc0 = make_float4(0.f, 0.f, 0.f, 0.f);
    float4 acc1 = make_float4(0.f, 0.f, 0.f, 0.f);

    for (int e = beg; e < end; e++) {
        int   id = g_perm[e];
        int   c  = cols[id];
        float v  = vals[id];
        const float4* src = (const float4*)(g_msg + (size_t)c * DOUT);
        float4 p0 = src[lane];
        float4 p1 = src[lane + 32];
        acc0.x = fmaf(v, p0.x, acc0.x);
        acc0.y = fmaf(v, p0.y, acc0.y);
        acc0.z = fmaf(v, p0.z, acc0.z);
        acc0.w = fmaf(v, p0.w, acc0.w);
        acc1.x = fmaf(v, p1.x, acc1.x);
        acc1.y = fmaf(v, p1.y, acc1.y);
        acc1.z = fmaf(v, p1.z, acc1.z);
        acc1.w = fmaf(v, p1.w, acc1.w);
    }

    // ELU
    acc0.x = acc0.x > 0.f ? acc0.x : expm1f(acc0.x);
    acc0.y = acc0.y > 0.f ? acc0.y : expm1f(acc0.y);
    acc0.z = acc0.z > 0.f ? acc0.z : expm1f(acc0.z);
    acc0.w = acc0.w > 0.f ? acc0.w : expm1f(acc0.w);
    acc1.x = acc1.x > 0.f ? acc1.x : expm1f(acc1.x);
    acc1.y = acc1.y > 0.f ? acc1.y : expm1f(acc1.y);
    acc1.z = acc1.z > 0.f ? acc1.z : expm1f(acc1.z);
    acc1.w = acc1.w > 0.f ? acc1.w : expm1f(acc1.w);

    float4* dst = (float4*)(out + (size_t)row * DOUT);
    dst[lane]      = acc0;
    dst[lane + 32] = acc1;
}

// ---------------------------------------------------------------------------
// Launch. Inputs: x_0, x_1(unused), nb_rows, nb_cols, nb_vals, weight.
// Output: float32 [N1, DOUT].
// ---------------------------------------------------------------------------
extern "C" void kernel_launch(void* const* d_in, const int* in_sizes, int n_in,
                              void* d_out, int out_size)
{
    const float* x_0     = (const float*)d_in[0];
    const int*   nb_rows = (const int*)  d_in[2];
    const int*   nb_cols = (const int*)  d_in[3];
    const float* nb_vals = (const float*)d_in[4];
    const float* weight  = (const float*)d_in[5];
    float*       out     = (float*)d_out;

    // GEMM (independent of CSR build; launched first)
    dim3 ggrid(DOUT / 128, (N0 + 127) / 128);
    sgemm_kernel<<<ggrid, 256>>>(x_0, weight);

    // CSR build
    zero_count_kernel<<<(N1 + 255) / 256, 256>>>();
    count_kernel<<<(NNZE + 255) / 256, 256>>>(nb_rows);
    scan1_kernel<<<NB_SCAN, SCAN_B>>>();
    scan2_kernel<<<1, 256>>>();
    scan3_kernel<<<NB_SCAN, SCAN_B>>>();
    fill_kernel<<<(NNZE + 255) / 256, 256>>>(nb_rows);

    // Fused gather + segment-sum + ELU, one warp per row, no atomics.
    int ablocks = (N1 * 32 + 255) / 256;
    aggregate_kernel<<<ablocks, 256>>>(nb_cols, nb_vals, out);
}

// round 8
// speedup vs baseline: 2.1408x; 1.6584x over previous
#include <cuda_runtime.h>
#include <cuda_bf16.h>
#include <math.h>
#include <stdint.h>

// Problem constants (fixed by the reference)
#define N0   100000
#define N1   200000
#define NNZE 400000
#define DIN  256
#define DOUT 256

#define N0PAD 100096                 // 782 * 128
#define SCAN_B 1024
#define NB_SCAN ((N1 + SCAN_B - 1) / SCAN_B)   // 196

// ---------------------------------------------------------------------------
// Scratch (allocation-free __device__ globals)
// ---------------------------------------------------------------------------
__device__ float g_msg[(size_t)N0 * DOUT];     // 102.4 MB
__device__ int   g_count[N1];
__device__ int   g_off[N1 + 1];
__device__ int   g_cursor[N1];
__device__ int   g_scol[NNZE];
__device__ float g_sval[NNZE];
__device__ int   g_bsum[256];
__device__ int   g_boff[256];

// Pre-split bf16 operands (hi + lo, x = hi + lo to ~2^-18 rel)
__device__ __align__(16) __nv_bfloat16 g_a_hi[(size_t)N0PAD * DIN];   // 51.2 MB
__device__ __align__(16) __nv_bfloat16 g_a_lo[(size_t)N0PAD * DIN];
__device__ __align__(16) __nv_bfloat16 g_wt_hi[DOUT * DIN];           // W^T [n][k]
__device__ __align__(16) __nv_bfloat16 g_wt_lo[DOUT * DIN];

// ---------------------------------------------------------------------------
// Helpers (all baseline PTX, compiles for compute_103)
// ---------------------------------------------------------------------------
__device__ __forceinline__ uint32_t smem_u32(const void* p) {
    uint32_t a;
    asm("{ .reg .u64 t; cvta.to.shared.u64 t, %1; cvt.u32.u64 %0, t; }"
        : "=r"(a) : "l"(p));
    return a;
}
// 64B-row swizzle: XOR 16B-column bits [5:4] with row bits [8:7]
__device__ __forceinline__ uint32_t swz(uint32_t o) { return o ^ ((o >> 3) & 0x30); }

#define CP16(dst, src) \
    asm volatile("cp.async.cg.shared.global [%0], [%1], 16;" \
                 :: "r"(dst), "l"(src))
#define CP_COMMIT() asm volatile("cp.async.commit_group;")
#define CP_WAIT2()  asm volatile("cp.async.wait_group 2;")
#define CP_WAIT0()  asm volatile("cp.async.wait_group 0;")

#define LDSM4(r0, r1, r2, r3, addr) \
    asm volatile("ldmatrix.sync.aligned.m8n8.x4.shared.b16 {%0,%1,%2,%3}, [%4];" \
                 : "=r"(r0), "=r"(r1), "=r"(r2), "=r"(r3) : "r"(addr))

#define MMA_BF16(d, a, b) \
    asm volatile("mma.sync.aligned.m16n8k16.row.col.f32.bf16.bf16.f32 " \
                 "{%0,%1,%2,%3}, {%4,%5,%6,%7}, {%8,%9}, {%0,%1,%2,%3};" \
                 : "+f"((d)[0]), "+f"((d)[1]), "+f"((d)[2]), "+f"((d)[3]) \
                 : "r"((a)[0]), "r"((a)[1]), "r"((a)[2]), "r"((a)[3]), \
                   "r"((b)[0]), "r"((b)[1]))

// SMEM pipeline: 3 stages x (A_hi 8K | A_lo 8K | B_hi 8K | B_lo 8K) = 96 KB
#define STAGE_BYTES 32768
#define NSTAGES 3
#define GEMM_SMEM (NSTAGES * STAGE_BYTES)
#define KCHUNKS 8        // 256 / 32

// ---------------------------------------------------------------------------
// Prep kernels: split fp32 -> bf16 hi/lo in global.
// ---------------------------------------------------------------------------
__device__ __forceinline__ void split2(float x, float y,
                                       __nv_bfloat162* hi, __nv_bfloat162* lo)
{
    __nv_bfloat16 hx = __float2bfloat16(x);
    __nv_bfloat16 hy = __float2bfloat16(y);
    *hi = __nv_bfloat162(hx, hy);
    *lo = __nv_bfloat162(__float2bfloat16(x - __bfloat162float(hx)),
                         __float2bfloat16(y - __bfloat162float(hy)));
}

__global__ __launch_bounds__(256)
void a_prep_kernel(const float* __restrict__ x0)
{
    size_t idx = (size_t)blockIdx.x * 256 + threadIdx.x;   // float4 slot
    if (idx >= (size_t)N0PAD * (DIN / 4)) return;
    int row = (int)(idx >> 6);
    int c4  = (int)(idx & 63) * 4;
    float4 v = make_float4(0.f, 0.f, 0.f, 0.f);
    if (row < N0) v = *(const float4*)(x0 + (size_t)row * DIN + c4);
    __nv_bfloat162 h0, l0, h1, l1;
    split2(v.x, v.y, &h0, &l0);
    split2(v.z, v.w, &h1, &l1);
    size_t o = (size_t)row * DIN + c4;
    *(__nv_bfloat162*)(g_a_hi + o)     = h0;
    *(__nv_bfloat162*)(g_a_hi + o + 2) = h1;
    *(__nv_bfloat162*)(g_a_lo + o)     = l0;
    *(__nv_bfloat162*)(g_a_lo + o + 2) = l1;
}

__global__ __launch_bounds__(256)
void wt_prep_kernel(const float* __restrict__ W)
{
    int idx = blockIdx.x * blockDim.x + threadIdx.x;
    if (idx >= DIN * DOUT) return;
    int n = idx >> 8;
    int k = idx & 255;
    float v = W[(size_t)k * DOUT + n];
    __nv_bfloat16 hi = __float2bfloat16(v);
    __nv_bfloat16 lo = __float2bfloat16(v - __bfloat162float(hi));
    g_wt_hi[n * DIN + k] = hi;
    g_wt_lo[n * DIN + k] = lo;
}

// ---------------------------------------------------------------------------
// Tensor-core (mma.sync bf16, split 3-pass) GEMM:
//   g_msg[128 x 128 per CTA] = x_0 @ W
// Block 128x128, BK=32, 8 warps (2x4), warp tile 64x32, cp.async 3-stage.
// ---------------------------------------------------------------------------
__global__ __launch_bounds__(256)
void gemm_mma_kernel()
{
    extern __shared__ char smem[];
    const uint32_t sb = smem_u32(smem);
    const int tid  = threadIdx.x;
    const int lane = tid & 31;
    const int warp = tid >> 5;
    const int wm = (warp & 1) * 64;       // warp m offset in block tile
    const int wn = (warp >> 1) * 32;      // warp n offset
    const int blockRow = blockIdx.y * 128;
    const int blockCol = blockIdx.x * 128;

    float acc[4][4][4];
    #pragma unroll
    for (int i = 0; i < 4; i++)
        #pragma unroll
        for (int j = 0; j < 4; j++)
            #pragma unroll
            for (int r = 0; r < 4; r++) acc[i][j][r] = 0.f;

    // --- async issue of one 32-wide K chunk into stage s ---
    auto issue = [&](int chunk, int s) {
        uint32_t s0 = sb + s * STAGE_BYTES;
        #pragma unroll
        for (int rep = 0; rep < 2; rep++) {
            int slot = tid + rep * 256;          // 0..511
            int row  = slot >> 2;                // 0..127
            int u    = slot & 3;                 // 16B unit within 64B row
            uint32_t so = swz((uint32_t)(row * 64 + u * 16));
            size_t ga = (size_t)(blockRow + row) * DIN + chunk * 32 + u * 8;
            size_t gb = (size_t)(blockCol + row) * DIN + chunk * 32 + u * 8;
            CP16(s0 + so,         (const char*)(g_a_hi + ga));
            CP16(s0 + 8192 + so,  (const char*)(g_a_lo + ga));
            CP16(s0 + 16384 + so, (const char*)(g_wt_hi + gb));
            CP16(s0 + 24576 + so, (const char*)(g_wt_lo + gb));
        }
    };

    issue(0, 0); CP_COMMIT();
    issue(1, 1); CP_COMMIT();

    for (int c = 0; c < KCHUNKS; c++) {
        if (c + 2 < KCHUNKS) issue(c + 2, (c + 2) % NSTAGES);
        CP_COMMIT();            // empty group when no issue: keeps count uniform
        CP_WAIT2();             // chunk c's group complete
        __syncthreads();

        uint32_t base = sb + (c % NSTAGES) * STAGE_BYTES;

        #pragma unroll
        for (int kk = 0; kk < 2; kk++) {
            // lane-dependent ldmatrix source offsets
            uint32_t a_kb   = (uint32_t)(kk * 32 + ((lane >> 4) << 4));
            uint32_t a_roff = (uint32_t)((lane & 15) * 64);
            uint32_t b_kb   = (uint32_t)(kk * 32 + (((lane >> 3) & 1) << 4));
            uint32_t b_roff = (uint32_t)(((lane & 7) + ((lane >> 4) << 3)) * 64);

            uint32_t ah[4][4], bh[4][2];
            #pragma unroll
            for (int mt = 0; mt < 4; mt++) {
                uint32_t off = swz((uint32_t)((wm + mt * 16) * 64) + a_roff + a_kb);
                LDSM4(ah[mt][0], ah[mt][1], ah[mt][2], ah[mt][3], base + off);
            }
            #pragma unroll
            for (int np = 0; np < 2; np++) {
                uint32_t off = swz((uint32_t)((wn + np * 16) * 64) + b_roff + b_kb);
                LDSM4(bh[2*np][0], bh[2*np][1], bh[2*np+1][0], bh[2*np+1][1],
                      base + 16384 + off);
            }
            // pass 1: hi * hi
            #pragma unroll
            for (int mt = 0; mt < 4; mt++)
                #pragma unroll
                for (int nt = 0; nt < 4; nt++)
                    MMA_BF16(acc[mt][nt], ah[mt], bh[nt]);

            // pass 2: hi * lo
            {
                uint32_t bl[4][2];
                #pragma unroll
                for (int np = 0; np < 2; np++) {
                    uint32_t off = swz((uint32_t)((wn + np * 16) * 64) + b_roff + b_kb);
                    LDSM4(bl[2*np][0], bl[2*np][1], bl[2*np+1][0], bl[2*np+1][1],
                          base + 24576 + off);
                }
                #pragma unroll
                for (int mt = 0; mt < 4; mt++)
                    #pragma unroll
                    for (int nt = 0; nt < 4; nt++)
                        MMA_BF16(acc[mt][nt], ah[mt], bl[nt]);
            }
            // pass 3: lo * hi
            {
                uint32_t al[4][4];
                #pragma unroll
                for (int mt = 0; mt < 4; mt++) {
                    uint32_t off = swz((uint32_t)((wm + mt * 16) * 64) + a_roff + a_kb);
                    LDSM4(al[mt][0], al[mt][1], al[mt][2], al[mt][3],
                          base + 8192 + off);
                }
                #pragma unroll
                for (int mt = 0; mt < 4; mt++)
                    #pragma unroll
                    for (int nt = 0; nt < 4; nt++)
                        MMA_BF16(acc[mt][nt], al[mt], bh[nt]);
            }
        }
        __syncthreads();
    }
    CP_WAIT0();

    // Epilogue: c-fragment -> g_msg fp32
    #pragma unroll
    for (int mt = 0; mt < 4; mt++) {
        #pragma unroll
        for (int nt = 0; nt < 4; nt++) {
            int r0  = blockRow + wm + mt * 16 + (lane >> 2);
            int col = blockCol + wn + nt * 8 + (lane & 3) * 2;
            if (r0 < N0)
                *(float2*)(g_msg + (size_t)r0 * DOUT + col) =
                    make_float2(acc[mt][nt][0], acc[mt][nt][1]);
            if (r0 + 8 < N0)
                *(float2*)(g_msg + (size_t)(r0 + 8) * DOUT + col) =
                    make_float2(acc[mt][nt][2], acc[mt][nt][3]);
        }
    }
}

// ---------------------------------------------------------------------------
// CSR build
// ---------------------------------------------------------------------------
__global__ __launch_bounds__(256)
void zero_count_kernel()
{
    int i = blockIdx.x * blockDim.x + threadIdx.x;
    if (i < N1) g_count[i] = 0;
}

__global__ __launch_bounds__(256)
void count_kernel(const int* __restrict__ rows)
{
    int e = blockIdx.x * blockDim.x + threadIdx.x;
    if (e < NNZE) atomicAdd(&g_count[rows[e]], 1);
}

__global__ __launch_bounds__(SCAN_B)
void scan1_kernel()
{
    __shared__ int s[SCAN_B];
    int tid = threadIdx.x;
    int i = blockIdx.x * SCAN_B + tid;
    int v = (i < N1) ? g_count[i] : 0;
    s[tid] = v;
    __syncthreads();
    #pragma unroll
    for (int off = 1; off < SCAN_B; off <<= 1) {
        int t = (tid >= off) ? s[tid - off] : 0;
        __syncthreads();
        s[tid] += t;
        __syncthreads();
    }
    if (i < N1) g_off[i] = s[tid] - v;
    if (tid == SCAN_B - 1) g_bsum[blockIdx.x] = s[tid];
}

__global__ __launch_bounds__(256)
void scan2_kernel()
{
    __shared__ int s[256];
    int tid = threadIdx.x;
    int v = (tid < NB_SCAN) ? g_bsum[tid] : 0;
    s[tid] = v;
    __syncthreads();
    #pragma unroll
    for (int off = 1; off < 256; off <<= 1) {
        int t = (tid >= off) ? s[tid - off] : 0;
        __syncthreads();
        s[tid] += t;
        __syncthreads();
    }
    if (tid < NB_SCAN) g_boff[tid] = s[tid] - v;
}

__global__ __launch_bounds__(SCAN_B)
void scan3_kernel()
{
    int tid = threadIdx.x;
    int i = blockIdx.x * SCAN_B + tid;
    if (i < N1) {
        int val = g_off[i] + g_boff[blockIdx.x];
        g_off[i]    = val;
        g_cursor[i] = val;
    }
    if (i == 0) g_off[N1] = NNZE;
}

__global__ __launch_bounds__(256)
void fill_kernel(const int* __restrict__ rows,
                 const int* __restrict__ cols,
                 const float* __restrict__ vals)
{
    int e = blockIdx.x * blockDim.x + threadIdx.x;
    if (e < NNZE) {
        int pos = atomicAdd(&g_cursor[rows[e]], 1);
        g_scol[pos] = cols[e];
        g_sval[pos] = vals[e];
    }
}

// ---------------------------------------------------------------------------
// Aggregation: one warp per output row. Atomic-free, ELU fused, single write.
// ---------------------------------------------------------------------------
__global__ __launch_bounds__(256)
void aggregate_kernel(float* __restrict__ out)
{
    int row  = (blockIdx.x * blockDim.x + threadIdx.x) >> 5;
    int lane = threadIdx.x & 31;
    if (row >= N1) return;

    int beg = g_off[row];
    int end = g_off[row + 1];

    float4 acc0 = make_float4(0.f, 0.f, 0.f, 0.f);
    float4 acc1 = make_float4(0.f, 0.f, 0.f, 0.f);

    for (int e = beg; e < end; e++) {
        int   c = g_scol[e];
        float v = g_sval[e];
        const float4* src = (const float4*)(g_msg + (size_t)c * DOUT);
        float4 p0 = src[lane];
        float4 p1 = src[lane + 32];
        acc0.x = fmaf(v, p0.x, acc0.x);
        acc0.y = fmaf(v, p0.y, acc0.y);
        acc0.z = fmaf(v, p0.z, acc0.z);
        acc0.w = fmaf(v, p0.w, acc0.w);
        acc1.x = fmaf(v, p1.x, acc1.x);
        acc1.y = fmaf(v, p1.y, acc1.y);
        acc1.z = fmaf(v, p1.z, acc1.z);
        acc1.w = fmaf(v, p1.w, acc1.w);
    }

    acc0.x = acc0.x > 0.f ? acc0.x : expm1f(acc0.x);
    acc0.y = acc0.y > 0.f ? acc0.y : expm1f(acc0.y);
    acc0.z = acc0.z > 0.f ? acc0.z : expm1f(acc0.z);
    acc0.w = acc0.w > 0.f ? acc0.w : expm1f(acc0.w);
    acc1.x = acc1.x > 0.f ? acc1.x : expm1f(acc1.x);
    acc1.y = acc1.y > 0.f ? acc1.y : expm1f(acc1.y);
    acc1.z = acc1.z > 0.f ? acc1.z : expm1f(acc1.z);
    acc1.w = acc1.w > 0.f ? acc1.w : expm1f(acc1.w);

    float4* dst = (float4*)(out + (size_t)row * DOUT);
    dst[lane]      = acc0;
    dst[lane + 32] = acc1;
}

// ---------------------------------------------------------------------------
// Launch. Inputs: x_0, x_1(unused), nb_rows, nb_cols, nb_vals, weight.
// Output: float32 [N1, DOUT].
// ---------------------------------------------------------------------------
extern "C" void kernel_launch(void* const* d_in, const int* in_sizes, int n_in,
                              void* d_out, int out_size)
{
    const float* x_0     = (const float*)d_in[0];
    const int*   nb_rows = (const int*)  d_in[2];
    const int*   nb_cols = (const int*)  d_in[3];
    const float* nb_vals = (const float*)d_in[4];
    const float* weight  = (const float*)d_in[5];
    float*       out     = (float*)d_out;

    static bool attr_done = false;
    if (!attr_done) {
        cudaFuncSetAttribute(gemm_mma_kernel,
                             cudaFuncAttributeMaxDynamicSharedMemorySize, GEMM_SMEM);
        attr_done = true;
    }

    // Operand prep: split fp32 -> bf16 hi/lo.
    int ablocks = (int)(((size_t)N0PAD * (DIN / 4) + 255) / 256);
    a_prep_kernel<<<ablocks, 256>>>(x_0);
    wt_prep_kernel<<<(DIN * DOUT + 255) / 256, 256>>>(weight);

    // Tensor-core GEMM: grid (2 col-blocks, 782 row-blocks).
    dim3 ggrid(DOUT / 128, N0PAD / 128);
    gemm_mma_kernel<<<ggrid, 256, GEMM_SMEM>>>();

    // CSR build (independent of GEMM result).
    zero_count_kernel<<<(N1 + 255) / 256, 256>>>();
    count_kernel<<<(NNZE + 255) / 256, 256>>>(nb_rows);
    scan1_kernel<<<NB_SCAN, SCAN_B>>>();
    scan2_kernel<<<1, 256>>>();
    scan3_kernel<<<NB_SCAN, SCAN_B>>>();
    fill_kernel<<<(NNZE + 255) / 256, 256>>>(nb_rows, nb_cols, nb_vals);

    // Fused gather + segment-sum + ELU, one warp per row, no atomics.
    int gblocks = (N1 * 32 + 255) / 256;
    aggregate_kernel<<<gblocks, 256>>>(out);
}

// round 9
// speedup vs baseline: 2.1445x; 1.0017x over previous
#include <cuda_runtime.h>
#include <cuda_bf16.h>
#include <math.h>
#include <stdint.h>

// Problem constants (fixed by the reference)
#define N0   100000
#define N1   200000
#define NNZE 400000
#define DIN  256
#define DOUT 256

#define N0PAD 100096                 // 782 * 128
#define SCAN_B 1024
#define NB_SCAN ((N1 + SCAN_B - 1) / SCAN_B)   // 196

// ---------------------------------------------------------------------------
// Scratch (allocation-free __device__ globals)
// ---------------------------------------------------------------------------
__device__ float g_msg[(size_t)N0 * DOUT];     // 102.4 MB
__device__ int   g_count[N1];
__device__ int   g_off[N1 + 1];
__device__ int   g_cursor[N1];
__device__ int   g_scol[NNZE];
__device__ float g_sval[NNZE];
__device__ int   g_bsum[256];
__device__ int   g_boff[256];

// Pre-split bf16 operands (hi + lo, x = hi + lo to ~2^-18 rel)
__device__ __align__(16) __nv_bfloat16 g_a_hi[(size_t)N0PAD * DIN];   // 51.2 MB
__device__ __align__(16) __nv_bfloat16 g_a_lo[(size_t)N0PAD * DIN];
__device__ __align__(16) __nv_bfloat16 g_wt_hi[DOUT * DIN];           // W^T [n][k]
__device__ __align__(16) __nv_bfloat16 g_wt_lo[DOUT * DIN];

// ---------------------------------------------------------------------------
// Helpers (all baseline PTX, compiles for compute_103)
// ---------------------------------------------------------------------------
__device__ __forceinline__ uint32_t smem_u32(const void* p) {
    uint32_t a;
    asm("{ .reg .u64 t; cvta.to.shared.u64 t, %1; cvt.u32.u64 %0, t; }"
        : "=r"(a) : "l"(p));
    return a;
}
// 64B-row swizzle: XOR 16B-column bits [5:4] with row bits [8:7]
__device__ __forceinline__ uint32_t swz(uint32_t o) { return o ^ ((o >> 3) & 0x30); }

#define CP16(dst, src) \
    asm volatile("cp.async.cg.shared.global [%0], [%1], 16;" \
                 :: "r"(dst), "l"(src))
#define CP_COMMIT() asm volatile("cp.async.commit_group;")
#define CP_WAIT2()  asm volatile("cp.async.wait_group 2;")
#define CP_WAIT0()  asm volatile("cp.async.wait_group 0;")

#define LDSM4(r0, r1, r2, r3, addr) \
    asm volatile("ldmatrix.sync.aligned.m8n8.x4.shared.b16 {%0,%1,%2,%3}, [%4];" \
                 : "=r"(r0), "=r"(r1), "=r"(r2), "=r"(r3) : "r"(addr))

#define MMA_BF16(d, a, b) \
    asm volatile("mma.sync.aligned.m16n8k16.row.col.f32.bf16.bf16.f32 " \
                 "{%0,%1,%2,%3}, {%4,%5,%6,%7}, {%8,%9}, {%0,%1,%2,%3};" \
                 : "+f"((d)[0]), "+f"((d)[1]), "+f"((d)[2]), "+f"((d)[3]) \
                 : "r"((a)[0]), "r"((a)[1]), "r"((a)[2]), "r"((a)[3]), \
                   "r"((b)[0]), "r"((b)[1]))

// SMEM pipeline: 3 stages x (A_hi 8K | A_lo 8K | B_hi 8K | B_lo 8K) = 96 KB
#define STAGE_BYTES 32768
#define NSTAGES 3
#define GEMM_SMEM (NSTAGES * STAGE_BYTES)
#define KCHUNKS 8        // 256 / 32

// ---------------------------------------------------------------------------
// Prep kernels: split fp32 -> bf16 hi/lo in global.
// ---------------------------------------------------------------------------
__device__ __forceinline__ void split2(float x, float y,
                                       __nv_bfloat162* hi, __nv_bfloat162* lo)
{
    __nv_bfloat16 hx = __float2bfloat16(x);
    __nv_bfloat16 hy = __float2bfloat16(y);
    *hi = __nv_bfloat162(hx, hy);
    *lo = __nv_bfloat162(__float2bfloat16(x - __bfloat162float(hx)),
                         __float2bfloat16(y - __bfloat162float(hy)));
}

__global__ __launch_bounds__(256)
void a_prep_kernel(const float* __restrict__ x0)
{
    size_t idx = (size_t)blockIdx.x * 256 + threadIdx.x;   // float4 slot
    if (idx >= (size_t)N0PAD * (DIN / 4)) return;
    int row = (int)(idx >> 6);
    int c4  = (int)(idx & 63) * 4;
    float4 v = make_float4(0.f, 0.f, 0.f, 0.f);
    if (row < N0) v = *(const float4*)(x0 + (size_t)row * DIN + c4);
    __nv_bfloat162 h0, l0, h1, l1;
    split2(v.x, v.y, &h0, &l0);
    split2(v.z, v.w, &h1, &l1);
    size_t o = (size_t)row * DIN + c4;
    *(__nv_bfloat162*)(g_a_hi + o)     = h0;
    *(__nv_bfloat162*)(g_a_hi + o + 2) = h1;
    *(__nv_bfloat162*)(g_a_lo + o)     = l0;
    *(__nv_bfloat162*)(g_a_lo + o + 2) = l1;
}

__global__ __launch_bounds__(256)
void wt_prep_kernel(const float* __restrict__ W)
{
    int idx = blockIdx.x * blockDim.x + threadIdx.x;
    if (idx >= DIN * DOUT) return;
    int n = idx >> 8;
    int k = idx & 255;
    float v = W[(size_t)k * DOUT + n];
    __nv_bfloat16 hi = __float2bfloat16(v);
    __nv_bfloat16 lo = __float2bfloat16(v - __bfloat162float(hi));
    g_wt_hi[n * DIN + k] = hi;
    g_wt_lo[n * DIN + k] = lo;
}

// ---------------------------------------------------------------------------
// Tensor-core (mma.sync bf16, split 3-pass) GEMM:
//   g_msg[128 x 128 per CTA] = x_0 @ W
// Block 128x128, BK=32, 8 warps (2x4), warp tile 64x32, cp.async 3-stage.
// Register-lean pass order (A-frag array reused for hi then lo) so 2 CTAs/SM.
// ---------------------------------------------------------------------------
__global__ __launch_bounds__(256, 2)
void gemm_mma_kernel()
{
    extern __shared__ char smem[];
    const uint32_t sb = smem_u32(smem);
    const int tid  = threadIdx.x;
    const int lane = tid & 31;
    const int warp = tid >> 5;
    const int wm = (warp & 1) * 64;       // warp m offset in block tile
    const int wn = (warp >> 1) * 32;      // warp n offset
    const int blockRow = blockIdx.y * 128;
    const int blockCol = blockIdx.x * 128;

    float acc[4][4][4];
    #pragma unroll
    for (int i = 0; i < 4; i++)
        #pragma unroll
        for (int j = 0; j < 4; j++)
            #pragma unroll
            for (int r = 0; r < 4; r++) acc[i][j][r] = 0.f;

    // --- async issue of one 32-wide K chunk into stage s ---
    auto issue = [&](int chunk, int s) {
        uint32_t s0 = sb + s * STAGE_BYTES;
        #pragma unroll
        for (int rep = 0; rep < 2; rep++) {
            int slot = tid + rep * 256;          // 0..511
            int row  = slot >> 2;                // 0..127
            int u    = slot & 3;                 // 16B unit within 64B row
            uint32_t so = swz((uint32_t)(row * 64 + u * 16));
            size_t ga = (size_t)(blockRow + row) * DIN + chunk * 32 + u * 8;
            size_t gb = (size_t)(blockCol + row) * DIN + chunk * 32 + u * 8;
            CP16(s0 + so,         (const char*)(g_a_hi + ga));
            CP16(s0 + 8192 + so,  (const char*)(g_a_lo + ga));
            CP16(s0 + 16384 + so, (const char*)(g_wt_hi + gb));
            CP16(s0 + 24576 + so, (const char*)(g_wt_lo + gb));
        }
    };

    issue(0, 0); CP_COMMIT();
    issue(1, 1); CP_COMMIT();

    for (int c = 0; c < KCHUNKS; c++) {
        if (c + 2 < KCHUNKS) issue(c + 2, (c + 2) % NSTAGES);
        CP_COMMIT();            // empty group when no issue: keeps count uniform
        CP_WAIT2();             // chunk c's group complete
        __syncthreads();

        uint32_t base = sb + (c % NSTAGES) * STAGE_BYTES;

        #pragma unroll
        for (int kk = 0; kk < 2; kk++) {
            // lane-dependent ldmatrix source offsets
            uint32_t a_kb   = (uint32_t)(kk * 32 + ((lane >> 4) << 4));
            uint32_t a_roff = (uint32_t)((lane & 15) * 64);
            uint32_t b_kb   = (uint32_t)(kk * 32 + (((lane >> 3) & 1) << 4));
            uint32_t b_roff = (uint32_t)(((lane & 7) + ((lane >> 4) << 3)) * 64);

            uint32_t af[4][4];        // A fragments: hi for passes 1-2, lo for pass 3
            uint32_t bh[4][2], bl[4][2];

            #pragma unroll
            for (int mt = 0; mt < 4; mt++) {
                uint32_t off = swz((uint32_t)((wm + mt * 16) * 64) + a_roff + a_kb);
                LDSM4(af[mt][0], af[mt][1], af[mt][2], af[mt][3], base + off);
            }
            #pragma unroll
            for (int np = 0; np < 2; np++) {
                uint32_t off = swz((uint32_t)((wn + np * 16) * 64) + b_roff + b_kb);
                LDSM4(bh[2*np][0], bh[2*np][1], bh[2*np+1][0], bh[2*np+1][1],
                      base + 16384 + off);
            }
            // pass 1: hi * hi
            #pragma unroll
            for (int mt = 0; mt < 4; mt++)
                #pragma unroll
                for (int nt = 0; nt < 4; nt++)
                    MMA_BF16(acc[mt][nt], af[mt], bh[nt]);

            // pass 2: hi * lo
            #pragma unroll
            for (int np = 0; np < 2; np++) {
                uint32_t off = swz((uint32_t)((wn + np * 16) * 64) + b_roff + b_kb);
                LDSM4(bl[2*np][0], bl[2*np][1], bl[2*np+1][0], bl[2*np+1][1],
                      base + 24576 + off);
            }
            #pragma unroll
            for (int mt = 0; mt < 4; mt++)
                #pragma unroll
                for (int nt = 0; nt < 4; nt++)
                    MMA_BF16(acc[mt][nt], af[mt], bl[nt]);

            // pass 3: lo * hi  (reuse af[] for A-lo; A-hi dead)
            #pragma unroll
            for (int mt = 0; mt < 4; mt++) {
                uint32_t off = swz((uint32_t)((wm + mt * 16) * 64) + a_roff + a_kb);
                LDSM4(af[mt][0], af[mt][1], af[mt][2], af[mt][3],
                      base + 8192 + off);
            }
            #pragma unroll
            for (int mt = 0; mt < 4; mt++)
                #pragma unroll
                for (int nt = 0; nt < 4; nt++)
                    MMA_BF16(acc[mt][nt], af[mt], bh[nt]);
        }
        __syncthreads();
    }
    CP_WAIT0();

    // Epilogue: c-fragment -> g_msg fp32
    #pragma unroll
    for (int mt = 0; mt < 4; mt++) {
        #pragma unroll
        for (int nt = 0; nt < 4; nt++) {
            int r0  = blockRow + wm + mt * 16 + (lane >> 2);
            int col = blockCol + wn + nt * 8 + (lane & 3) * 2;
            if (r0 < N0)
                *(float2*)(g_msg + (size_t)r0 * DOUT + col) =
                    make_float2(acc[mt][nt][0], acc[mt][nt][1]);
            if (r0 + 8 < N0)
                *(float2*)(g_msg + (size_t)(r0 + 8) * DOUT + col) =
                    make_float2(acc[mt][nt][2], acc[mt][nt][3]);
        }
    }
}

// ---------------------------------------------------------------------------
// CSR build
// ---------------------------------------------------------------------------
__global__ __launch_bounds__(256)
void zero_count_kernel()
{
    int i = blockIdx.x * blockDim.x + threadIdx.x;
    if (i < N1) g_count[i] = 0;
}

__global__ __launch_bounds__(256)
void count_kernel(const int* __restrict__ rows)
{
    int e = blockIdx.x * blockDim.x + threadIdx.x;
    if (e < NNZE) atomicAdd(&g_count[rows[e]], 1);
}

__global__ __launch_bounds__(SCAN_B)
void scan1_kernel()
{
    __shared__ int s[SCAN_B];
    int tid = threadIdx.x;
    int i = blockIdx.x * SCAN_B + tid;
    int v = (i < N1) ? g_count[i] : 0;
    s[tid] = v;
    __syncthreads();
    #pragma unroll
    for (int off = 1; off < SCAN_B; off <<= 1) {
        int t = (tid >= off) ? s[tid - off] : 0;
        __syncthreads();
        s[tid] += t;
        __syncthreads();
    }
    if (i < N1) g_off[i] = s[tid] - v;
    if (tid == SCAN_B - 1) g_bsum[blockIdx.x] = s[tid];
}

__global__ __launch_bounds__(256)
void scan2_kernel()
{
    __shared__ int s[256];
    int tid = threadIdx.x;
    int v = (tid < NB_SCAN) ? g_bsum[tid] : 0;
    s[tid] = v;
    __syncthreads();
    #pragma unroll
    for (int off = 1; off < 256; off <<= 1) {
        int t = (tid >= off) ? s[tid - off] : 0;
        __syncthreads();
        s[tid] += t;
        __syncthreads();
    }
    if (tid < NB_SCAN) g_boff[tid] = s[tid] - v;
}

__global__ __launch_bounds__(SCAN_B)
void scan3_kernel()
{
    int tid = threadIdx.x;
    int i = blockIdx.x * SCAN_B + tid;
    if (i < N1) {
        int val = g_off[i] + g_boff[blockIdx.x];
        g_off[i]    = val;
        g_cursor[i] = val;
    }
    if (i == 0) g_off[N1] = NNZE;
}

__global__ __launch_bounds__(256)
void fill_kernel(const int* __restrict__ rows,
                 const int* __restrict__ cols,
                 const float* __restrict__ vals)
{
    int e = blockIdx.x * blockDim.x + threadIdx.x;
    if (e < NNZE) {
        int pos = atomicAdd(&g_cursor[rows[e]], 1);
        g_scol[pos] = cols[e];
        g_sval[pos] = vals[e];
    }
}

// ---------------------------------------------------------------------------
// Aggregation: one warp per output row. Atomic-free, ELU fused, single write.
// ---------------------------------------------------------------------------
__global__ __launch_bounds__(256)
void aggregate_kernel(float* __restrict__ out)
{
    int row  = (blockIdx.x * blockDim.x + threadIdx.x) >> 5;
    int lane = threadIdx.x & 31;
    if (row >= N1) return;

    int beg = g_off[row];
    int end = g_off[row + 1];

    float4 acc0 = make_float4(0.f, 0.f, 0.f, 0.f);
    float4 acc1 = make_float4(0.f, 0.f, 0.f, 0.f);

    for (int e = beg; e < end; e++) {
        int   c = g_scol[e];
        float v = g_sval[e];
        const float4* src = (const float4*)(g_msg + (size_t)c * DOUT);
        float4 p0 = src[lane];
        float4 p1 = src[lane + 32];
        acc0.x = fmaf(v, p0.x, acc0.x);
        acc0.y = fmaf(v, p0.y, acc0.y);
        acc0.z = fmaf(v, p0.z, acc0.z);
        acc0.w = fmaf(v, p0.w, acc0.w);
        acc1.x = fmaf(v, p1.x, acc1.x);
        acc1.y = fmaf(v, p1.y, acc1.y);
        acc1.z = fmaf(v, p1.z, acc1.z);
        acc1.w = fmaf(v, p1.w, acc1.w);
    }

    acc0.x = acc0.x > 0.f ? acc0.x : expm1f(acc0.x);
    acc0.y = acc0.y > 0.f ? acc0.y : expm1f(acc0.y);
    acc0.z = acc0.z > 0.f ? acc0.z : expm1f(acc0.z);
    acc0.w = acc0.w > 0.f ? acc0.w : expm1f(acc0.w);
    acc1.x = acc1.x > 0.f ? acc1.x : expm1f(acc1.x);
    acc1.y = acc1.y > 0.f ? acc1.y : expm1f(acc1.y);
    acc1.z = acc1.z > 0.f ? acc1.z : expm1f(acc1.z);
    acc1.w = acc1.w > 0.f ? acc1.w : expm1f(acc1.w);

    float4* dst = (float4*)(out + (size_t)row * DOUT);
    dst[lane]      = acc0;
    dst[lane + 32] = acc1;
}

// ---------------------------------------------------------------------------
// Launch. Inputs: x_0, x_1(unused), nb_rows, nb_cols, nb_vals, weight.
// Output: float32 [N1, DOUT].
// NOTE: gemm placed at launch position 4 so the ncu capture window (which
// landed on launch #4 last round) profiles the GEMM.
// ---------------------------------------------------------------------------
extern "C" void kernel_launch(void* const* d_in, const int* in_sizes, int n_in,
                              void* d_out, int out_size)
{
    const float* x_0     = (const float*)d_in[0];
    const int*   nb_rows = (const int*)  d_in[2];
    const int*   nb_cols = (const int*)  d_in[3];
    const float* nb_vals = (const float*)d_in[4];
    const float* weight  = (const float*)d_in[5];
    float*       out     = (float*)d_out;

    static bool attr_done = false;
    if (!attr_done) {
        cudaFuncSetAttribute(gemm_mma_kernel,
                             cudaFuncAttributeMaxDynamicSharedMemorySize, GEMM_SMEM);
        attr_done = true;
    }

    // (1) Operand prep: split fp32 -> bf16 hi/lo.
    int ablocks = (int)(((size_t)N0PAD * (DIN / 4) + 255) / 256);
    a_prep_kernel<<<ablocks, 256>>>(x_0);
    // (2)
    wt_prep_kernel<<<(DIN * DOUT + 255) / 256, 256>>>(weight);
    // (3) independent CSR-prep launch, keeps gemm at position 4
    zero_count_kernel<<<(N1 + 255) / 256, 256>>>();
    // (4) Tensor-core GEMM: grid (2 col-blocks, 782 row-blocks).
    dim3 ggrid(DOUT / 128, N0PAD / 128);
    gemm_mma_kernel<<<ggrid, 256, GEMM_SMEM>>>();
    // (5..9) CSR build (independent of GEMM result).
    count_kernel<<<(NNZE + 255) / 256, 256>>>(nb_rows);
    scan1_kernel<<<NB_SCAN, SCAN_B>>>();
    scan2_kernel<<<1, 256>>>();
    scan3_kernel<<<NB_SCAN, SCAN_B>>>();
    fill_kernel<<<(NNZE + 255) / 256, 256>>>(nb_rows, nb_cols, nb_vals);
    // (10) Fused gather + segment-sum + ELU, one warp per row, no atomics.
    int gblocks = (N1 * 32 + 255) / 256;
    aggregate_kernel<<<gblocks, 256>>>(out);
}

// round 10
// speedup vs baseline: 2.3456x; 1.0938x over previous
#include <cuda_runtime.h>
#include <cuda_bf16.h>
#include <math.h>
#include <stdint.h>

// Problem constants (fixed by the reference)
#define N0   100000
#define N1   200000
#define NNZE 400000
#define DIN  256
#define DOUT 256

#define N0PAD 100096                 // 782 * 128
#define SCAN_B 1024
#define NB_SCAN ((N1 + SCAN_B - 1) / SCAN_B)   // 196

// ---------------------------------------------------------------------------
// Scratch (allocation-free __device__ globals)
// ---------------------------------------------------------------------------
__device__ float g_msg[(size_t)N0 * DOUT];     // 102.4 MB
__device__ int   g_count[N1];
__device__ int   g_off[N1 + 1];
__device__ int   g_cursor[N1];
__device__ int   g_scol[NNZE];
__device__ float g_sval[NNZE];
__device__ int   g_bsum[256];
__device__ int   g_boff[256];

// W^T pre-split into bf16 hi/lo (tiny: 256 KB total)
__device__ __align__(16) __nv_bfloat16 g_wt_hi[DOUT * DIN];           // W^T [n][k]
__device__ __align__(16) __nv_bfloat16 g_wt_lo[DOUT * DIN];

// ---------------------------------------------------------------------------
// Helpers (all baseline PTX, compiles for compute_103)
// ---------------------------------------------------------------------------
__device__ __forceinline__ uint32_t smem_u32(const void* p) {
    uint32_t a;
    asm("{ .reg .u64 t; cvta.to.shared.u64 t, %1; cvt.u32.u64 %0, t; }"
        : "=r"(a) : "l"(p));
    return a;
}
// 64B-row swizzle: XOR 16B-column bits [5:4] with row bits [8:7]
__device__ __forceinline__ uint32_t swz(uint32_t o) { return o ^ ((o >> 3) & 0x30); }

#define CP16(dst, src) \
    asm volatile("cp.async.cg.shared.global [%0], [%1], 16;" \
                 :: "r"(dst), "l"(src))
// src-size form: n==0 -> zero-fill (pad rows)
#define CP16Z(dst, src, n) \
    asm volatile("cp.async.cg.shared.global [%0], [%1], 16, %2;" \
                 :: "r"(dst), "l"(src), "r"(n))
#define CP_COMMIT() asm volatile("cp.async.commit_group;")
#define CP_WAIT1()  asm volatile("cp.async.wait_group 1;")
#define CP_WAIT0()  asm volatile("cp.async.wait_group 0;")

#define LDSM4(r0, r1, r2, r3, addr) \
    asm volatile("ldmatrix.sync.aligned.m8n8.x4.shared.b16 {%0,%1,%2,%3}, [%4];" \
                 : "=r"(r0), "=r"(r1), "=r"(r2), "=r"(r3) : "r"(addr))

#define MMA_BF16(d, a, b) \
    asm volatile("mma.sync.aligned.m16n8k16.row.col.f32.bf16.bf16.f32 " \
                 "{%0,%1,%2,%3}, {%4,%5,%6,%7}, {%8,%9}, {%0,%1,%2,%3};" \
                 : "+f"((d)[0]), "+f"((d)[1]), "+f"((d)[2]), "+f"((d)[3]) \
                 : "r"((a)[0]), "r"((a)[1]), "r"((a)[2]), "r"((a)[3]), \
                   "r"((b)[0]), "r"((b)[1]))

// Stage layout (48 KB per stage, 2 stages = 96 KB):
//   [0      :16384) A fp32 staging (128 rows x 32 cols, linear 16B slots)
//   [16384  :24576) A hi bf16 (swizzled 64B rows)
//   [24576  :32768) A lo bf16
//   [32768  :40960) B hi bf16
//   [40960  :49152) B lo bf16
#define SM_AF32 0
#define SM_AHI  16384
#define SM_ALO  24576
#define SM_BHI  32768
#define SM_BLO  40960
#define STAGE_BYTES 49152
#define NSTAGES 2
#define GEMM_SMEM (NSTAGES * STAGE_BYTES)     // 98304
#define KCHUNKS 8        // 256 / 32

// ---------------------------------------------------------------------------
// W prep: transpose + split fp32 -> bf16 hi/lo (tiny, one launch).
// ---------------------------------------------------------------------------
__global__ __launch_bounds__(256)
void wt_prep_kernel(const float* __restrict__ W)
{
    int idx = blockIdx.x * blockDim.x + threadIdx.x;
    if (idx >= DIN * DOUT) return;
    int n = idx >> 8;
    int k = idx & 255;
    float v = W[(size_t)k * DOUT + n];
    __nv_bfloat16 hi = __float2bfloat16(v);
    __nv_bfloat16 lo = __float2bfloat16(v - __bfloat162float(hi));
    g_wt_hi[n * DIN + k] = hi;
    g_wt_lo[n * DIN + k] = lo;
}

// ---------------------------------------------------------------------------
// Tensor-core (mma.sync bf16, split 3-pass) GEMM with FUSED A split:
//   g_msg[128 x 128 per CTA] = x_0 @ W
// Block 128x128, BK=32, 8 warps (2x4), warp tile 64x32.
// Mainloop: cp.async fp32 A chunk -> staging, convert to bf16 hi/lo smem
// in-kernel (fma/alu pipes are idle), 2-stage pipeline, 2 CTAs/SM.
// ---------------------------------------------------------------------------
__global__ __launch_bounds__(256, 2)
void gemm_mma_kernel(const float* __restrict__ x0)
{
    extern __shared__ char smem[];
    const uint32_t sb = smem_u32(smem);
    const int tid  = threadIdx.x;
    const int lane = tid & 31;
    const int warp = tid >> 5;
    const int wm = (warp & 1) * 64;       // warp m offset in block tile
    const int wn = (warp >> 1) * 32;      // warp n offset
    const int blockRow = blockIdx.y * 128;
    const int blockCol = blockIdx.x * 128;

    float acc[4][4][4];
    #pragma unroll
    for (int i = 0; i < 4; i++)
        #pragma unroll
        for (int j = 0; j < 4; j++)
            #pragma unroll
            for (int r = 0; r < 4; r++) acc[i][j][r] = 0.f;

    // --- async issue of one 32-wide K chunk into stage s ---
    auto issue = [&](int chunk, int s) {
        uint32_t s0 = sb + s * STAGE_BYTES;
        // A fp32: 1024 float4 slots, linear layout, zero-fill pad rows.
        #pragma unroll
        for (int rep = 0; rep < 4; rep++) {
            int slot = tid + rep * 256;          // 0..1023
            int row  = slot >> 3;                // 0..127
            int u    = slot & 7;                 // float4 within 32-col row
            int grow = blockRow + row;
            int ok   = (grow < N0) ? 16 : 0;
            const float* src = x0 + (size_t)(ok ? grow : 0) * DIN + chunk * 32 + u * 4;
            CP16Z(s0 + SM_AF32 + slot * 16, (const char*)src, ok);
        }
        // B hi/lo: 512 float4 each, swizzled 64B rows.
        #pragma unroll
        for (int rep = 0; rep < 2; rep++) {
            int slot = tid + rep * 256;          // 0..511
            int row  = slot >> 2;                // 0..127
            int u    = slot & 3;                 // 16B unit within 64B row
            uint32_t so = swz((uint32_t)(row * 64 + u * 16));
            size_t gb = (size_t)(blockCol + row) * DIN + chunk * 32 + u * 8;
            CP16(s0 + SM_BHI + so, (const char*)(g_wt_hi + gb));
            CP16(s0 + SM_BLO + so, (const char*)(g_wt_lo + gb));
        }
    };

    issue(0, 0); CP_COMMIT();

    for (int c = 0; c < KCHUNKS; c++) {
        if (c + 1 < KCHUNKS) issue(c + 1, (c + 1) & 1);
        CP_COMMIT();            // empty group when no issue: keeps count uniform
        CP_WAIT1();             // chunk c's group complete (<=1 outstanding)
        __syncthreads();

        uint32_t base = sb + (c & 1) * STAGE_BYTES;

        // ---- Convert A fp32 staging -> bf16 hi/lo swizzled smem.
        // Each thread: 4 float4 (lane-consecutive slots -> conflict-free LDS).
        #pragma unroll
        for (int j = 0; j < 4; j++) {
            int slot = tid + j * 256;            // 0..1023
            int row  = slot >> 3;
            int u    = slot & 7;
            float4 v = *(const float4*)(smem + (base - sb) + SM_AF32 + slot * 16);
            __nv_bfloat16 h0 = __float2bfloat16(v.x);
            __nv_bfloat16 h1 = __float2bfloat16(v.y);
            __nv_bfloat16 h2 = __float2bfloat16(v.z);
            __nv_bfloat16 h3 = __float2bfloat16(v.w);
            __nv_bfloat162 hp0(h0, h1), hp1(h2, h3);
            __nv_bfloat162 lp0(__float2bfloat16(v.x - __bfloat162float(h0)),
                               __float2bfloat16(v.y - __bfloat162float(h1)));
            __nv_bfloat162 lp1(__float2bfloat16(v.z - __bfloat162float(h2)),
                               __float2bfloat16(v.w - __bfloat162float(h3)));
            uint32_t b16 = swz((uint32_t)(row * 64 + (u >> 1) * 16)) + (u & 1) * 8;
            char* dst = smem + (base - sb);
            *(__nv_bfloat162*)(dst + SM_AHI + b16)     = hp0;
            *(__nv_bfloat162*)(dst + SM_AHI + b16 + 4) = hp1;
            *(__nv_bfloat162*)(dst + SM_ALO + b16)     = lp0;
            *(__nv_bfloat162*)(dst + SM_ALO + b16 + 4) = lp1;
        }
        __syncthreads();

        #pragma unroll
        for (int kk = 0; kk < 2; kk++) {
            // lane-dependent ldmatrix source offsets
            uint32_t a_kb   = (uint32_t)(kk * 32 + ((lane >> 4) << 4));
            uint32_t a_roff = (uint32_t)((lane & 15) * 64);
            uint32_t b_kb   = (uint32_t)(kk * 32 + (((lane >> 3) & 1) << 4));
            uint32_t b_roff = (uint32_t)(((lane & 7) + ((lane >> 4) << 3)) * 64);

            uint32_t af[4][4];        // A frags: hi for passes 1-2, lo for pass 3
            uint32_t bh[4][2], bl[4][2];

            #pragma unroll
            for (int mt = 0; mt < 4; mt++) {
                uint32_t off = swz((uint32_t)((wm + mt * 16) * 64) + a_roff + a_kb);
                LDSM4(af[mt][0], af[mt][1], af[mt][2], af[mt][3],
                      base + SM_AHI + off);
            }
            #pragma unroll
            for (int np = 0; np < 2; np++) {
                uint32_t off = swz((uint32_t)((wn + np * 16) * 64) + b_roff + b_kb);
                LDSM4(bh[2*np][0], bh[2*np][1], bh[2*np+1][0], bh[2*np+1][1],
                      base + SM_BHI + off);
            }
            // pass 1: hi * hi
            #pragma unroll
            for (int mt = 0; mt < 4; mt++)
                #pragma unroll
                for (int nt = 0; nt < 4; nt++)
                    MMA_BF16(acc[mt][nt], af[mt], bh[nt]);

            // pass 2: hi * lo
            #pragma unroll
            for (int np = 0; np < 2; np++) {
                uint32_t off = swz((uint32_t)((wn + np * 16) * 64) + b_roff + b_kb);
                LDSM4(bl[2*np][0], bl[2*np][1], bl[2*np+1][0], bl[2*np+1][1],
                      base + SM_BLO + off);
            }
            #pragma unroll
            for (int mt = 0; mt < 4; mt++)
                #pragma unroll
                for (int nt = 0; nt < 4; nt++)
                    MMA_BF16(acc[mt][nt], af[mt], bl[nt]);

            // pass 3: lo * hi  (reuse af[] for A-lo; A-hi dead)
            #pragma unroll
            for (int mt = 0; mt < 4; mt++) {
                uint32_t off = swz((uint32_t)((wm + mt * 16) * 64) + a_roff + a_kb);
                LDSM4(af[mt][0], af[mt][1], af[mt][2], af[mt][3],
                      base + SM_ALO + off);
            }
            #pragma unroll
            for (int mt = 0; mt < 4; mt++)
                #pragma unroll
                for (int nt = 0; nt < 4; nt++)
                    MMA_BF16(acc[mt][nt], af[mt], bh[nt]);
        }
        __syncthreads();    // protect this stage before iter c+1 issues into it
    }
    CP_WAIT0();

    // Epilogue: c-fragment -> g_msg fp32
    #pragma unroll
    for (int mt = 0; mt < 4; mt++) {
        #pragma unroll
        for (int nt = 0; nt < 4; nt++) {
            int r0  = blockRow + wm + mt * 16 + (lane >> 2);
            int col = blockCol + wn + nt * 8 + (lane & 3) * 2;
            if (r0 < N0)
                *(float2*)(g_msg + (size_t)r0 * DOUT + col) =
                    make_float2(acc[mt][nt][0], acc[mt][nt][1]);
            if (r0 + 8 < N0)
                *(float2*)(g_msg + (size_t)(r0 + 8) * DOUT + col) =
                    make_float2(acc[mt][nt][2], acc[mt][nt][3]);
        }
    }
}

// ---------------------------------------------------------------------------
// CSR build
// ---------------------------------------------------------------------------
__global__ __launch_bounds__(256)
void zero_count_kernel()
{
    int i = blockIdx.x * blockDim.x + threadIdx.x;
    if (i < N1) g_count[i] = 0;
}

__global__ __launch_bounds__(256)
void count_kernel(const int* __restrict__ rows)
{
    int e = blockIdx.x * blockDim.x + threadIdx.x;
    if (e < NNZE) atomicAdd(&g_count[rows[e]], 1);
}

__global__ __launch_bounds__(SCAN_B)
void scan1_kernel()
{
    __shared__ int s[SCAN_B];
    int tid = threadIdx.x;
    int i = blockIdx.x * SCAN_B + tid;
    int v = (i < N1) ? g_count[i] : 0;
    s[tid] = v;
    __syncthreads();
    #pragma unroll
    for (int off = 1; off < SCAN_B; off <<= 1) {
        int t = (tid >= off) ? s[tid - off] : 0;
        __syncthreads();
        s[tid] += t;
        __syncthreads();
    }
    if (i < N1) g_off[i] = s[tid] - v;
    if (tid == SCAN_B - 1) g_bsum[blockIdx.x] = s[tid];
}

__global__ __launch_bounds__(256)
void scan2_kernel()
{
    __shared__ int s[256];
    int tid = threadIdx.x;
    int v = (tid < NB_SCAN) ? g_bsum[tid] : 0;
    s[tid] = v;
    __syncthreads();
    #pragma unroll
    for (int off = 1; off < 256; off <<= 1) {
        int t = (tid >= off) ? s[tid - off] : 0;
        __syncthreads();
        s[tid] += t;
        __syncthreads();
    }
    if (tid < NB_SCAN) g_boff[tid] = s[tid] - v;
}

__global__ __launch_bounds__(SCAN_B)
void scan3_kernel()
{
    int tid = threadIdx.x;
    int i = blockIdx.x * SCAN_B + tid;
    if (i < N1) {
        int val = g_off[i] + g_boff[blockIdx.x];
        g_off[i]    = val;
        g_cursor[i] = val;
    }
    if (i == 0) g_off[N1] = NNZE;
}

__global__ __launch_bounds__(256)
void fill_kernel(const int* __restrict__ rows,
                 const int* __restrict__ cols,
                 const float* __restrict__ vals)
{
    int e = blockIdx.x * blockDim.x + threadIdx.x;
    if (e < NNZE) {
        int pos = atomicAdd(&g_cursor[rows[e]], 1);
        g_scol[pos] = cols[e];
        g_sval[pos] = vals[e];
    }
}

// ---------------------------------------------------------------------------
// Aggregation: one warp per output row. Atomic-free, ELU fused, single write.
// ---------------------------------------------------------------------------
__global__ __launch_bounds__(256)
void aggregate_kernel(float* __restrict__ out)
{
    int row  = (blockIdx.x * blockDim.x + threadIdx.x) >> 5;
    int lane = threadIdx.x & 31;
    if (row >= N1) return;

    int beg = g_off[row];
    int end = g_off[row + 1];

    float4 acc0 = make_float4(0.f, 0.f, 0.f, 0.f);
    float4 acc1 = make_float4(0.f, 0.f, 0.f, 0.f);

    for (int e = beg; e < end; e++) {
        int   c = g_scol[e];
        float v = g_sval[e];
        const float4* src = (const float4*)(g_msg + (size_t)c * DOUT);
        float4 p0 = src[lane];
        float4 p1 = src[lane + 32];
        acc0.x = fmaf(v, p0.x, acc0.x);
        acc0.y = fmaf(v, p0.y, acc0.y);
        acc0.z = fmaf(v, p0.z, acc0.z);
        acc0.w = fmaf(v, p0.w, acc0.w);
        acc1.x = fmaf(v, p1.x, acc1.x);
        acc1.y = fmaf(v, p1.y, acc1.y);
        acc1.z = fmaf(v, p1.z, acc1.z);
        acc1.w = fmaf(v, p1.w, acc1.w);
    }

    acc0.x = acc0.x > 0.f ? acc0.x : expm1f(acc0.x);
    acc0.y = acc0.y > 0.f ? acc0.y : expm1f(acc0.y);
    acc0.z = acc0.z > 0.f ? acc0.z : expm1f(acc0.z);
    acc0.w = acc0.w > 0.f ? acc0.w : expm1f(acc0.w);
    acc1.x = acc1.x > 0.f ? acc1.x : expm1f(acc1.x);
    acc1.y = acc1.y > 0.f ? acc1.y : expm1f(acc1.y);
    acc1.z = acc1.z > 0.f ? acc1.z : expm1f(acc1.z);
    acc1.w = acc1.w > 0.f ? acc1.w : expm1f(acc1.w);

    float4* dst = (float4*)(out + (size_t)row * DOUT);
    dst[lane]      = acc0;
    dst[lane + 32] = acc1;
}

// ---------------------------------------------------------------------------
// Launch. Inputs: x_0, x_1(unused), nb_rows, nb_cols, nb_vals, weight.
// Output: float32 [N1, DOUT].
// NOTE: gemm kept at launch position 4 so the ncu capture window (launch #4)
// profiles the GEMM again for a clean A/B comparison.
// ---------------------------------------------------------------------------
extern "C" void kernel_launch(void* const* d_in, const int* in_sizes, int n_in,
                              void* d_out, int out_size)
{
    const float* x_0     = (const float*)d_in[0];
    const int*   nb_rows = (const int*)  d_in[2];
    const int*   nb_cols = (const int*)  d_in[3];
    const float* nb_vals = (const float*)d_in[4];
    const float* weight  = (const float*)d_in[5];
    float*       out     = (float*)d_out;

    static bool attr_done = false;
    if (!attr_done) {
        cudaFuncSetAttribute(gemm_mma_kernel,
                             cudaFuncAttributeMaxDynamicSharedMemorySize, GEMM_SMEM);
        attr_done = true;
    }

    // (1) W prep (tiny).
    wt_prep_kernel<<<(DIN * DOUT + 255) / 256, 256>>>(weight);
    // (2) (3) independent CSR-prep launches (keep gemm at position 4).
    zero_count_kernel<<<(N1 + 255) / 256, 256>>>();
    count_kernel<<<(NNZE + 255) / 256, 256>>>(nb_rows);
    // (4) Tensor-core GEMM with fused A split: grid (2, 782).
    dim3 ggrid(DOUT / 128, N0PAD / 128);
    gemm_mma_kernel<<<ggrid, 256, GEMM_SMEM>>>(x_0);
    // (5..8) CSR build (independent of GEMM result).
    scan1_kernel<<<NB_SCAN, SCAN_B>>>();
    scan2_kernel<<<1, 256>>>();
    scan3_kernel<<<NB_SCAN, SCAN_B>>>();
    fill_kernel<<<(NNZE + 255) / 256, 256>>>(nb_rows, nb_cols, nb_vals);
    // (9) Fused gather + segment-sum + ELU, one warp per row, no atomics.
    int gblocks = (N1 * 32 + 255) / 256;
    aggregate_kernel<<<gblocks, 256>>>(out);
}